// round 1
// baseline (speedup 1.0000x reference)
#include <cuda_runtime.h>
#include <math.h>

// ---------------- problem constants ----------------
#define Bb   256
#define Ss   256
#define Dd   256
#define Hh   4
#define DHh  64
#define Ll   2
#define FF   1024               // 4*D
#define NROWS (Bb*Ss)           // 65536

// ---------------- scratch (__device__ globals; no allocation) ----------------
__device__ float g_x  [NROWS*Dd];
__device__ float g_q  [NROWS*Dd];
__device__ float g_k  [NROWS*Dd];
__device__ float g_v  [NROWS*Dd];
__device__ float g_ctx[NROWS*Dd];
__device__ float g_t  [NROWS*Dd];
__device__ float g_h  [NROWS*Dd];
__device__ float g_f1 [NROWS*FF];
__device__ float g_f2 [NROWS*Dd];

// ---------------- helpers ----------------
__device__ __forceinline__ float gelu_exact(float x) {
    return 0.5f * x * (1.0f + erff(x * 0.70710678118654752440f));
}

// mean + rstd over a 256-wide row, one block of 256 threads
__device__ __forceinline__ float2 rowStats256(float v) {
    float s = v, s2 = v * v;
    #pragma unroll
    for (int o = 16; o > 0; o >>= 1) {
        s  += __shfl_down_sync(0xffffffffu, s,  o);
        s2 += __shfl_down_sync(0xffffffffu, s2, o);
    }
    __shared__ float sh[8], sh2[8];
    int lane = threadIdx.x & 31, wid = threadIdx.x >> 5;
    if (lane == 0) { sh[wid] = s; sh2[wid] = s2; }
    __syncthreads();
    if (threadIdx.x < 32) {
        s  = (lane < 8) ? sh[lane]  : 0.0f;
        s2 = (lane < 8) ? sh2[lane] : 0.0f;
        #pragma unroll
        for (int o = 4; o > 0; o >>= 1) {
            s  += __shfl_down_sync(0xffffffffu, s,  o);
            s2 += __shfl_down_sync(0xffffffffu, s2, o);
        }
        if (lane == 0) { sh[0] = s; sh2[0] = s2; }
    }
    __syncthreads();
    float mu  = sh[0] * (1.0f / 256.0f);
    float var = sh2[0] * (1.0f / 256.0f) - mu * mu;
    return make_float2(mu, rsqrtf(var + 1e-5f));
}

// ---------------- kernel 1: embedding + LN (also init total) ----------------
__global__ void __launch_bounds__(256) embed_ln_kernel(
        const int* __restrict__ ids,
        const float* __restrict__ item_emb,
        const float* __restrict__ pos_emb,
        float* __restrict__ x, float* __restrict__ out)
{
    int row = blockIdx.x;
    int t   = threadIdx.x;
    int s   = row & (Ss - 1);
    int id  = ids[row];
    float v = item_emb[(long)id * Dd + t] + pos_emb[s * Dd + t];
    float2 st = rowStats256(v);
    float y = (v - st.x) * st.y;
    long o = (long)row * Dd + t;
    x[o] = y;
    out[o] = y;   // total = x0
}

// ---------------- kernel 2: tiled SGEMM, C = A@W + bias, optional exact GELU --
// BM=BN=128, BK=16, 256 threads, 8x8 per-thread microtile.
__global__ void __launch_bounds__(256) gemm_bias_kernel(
        const float* __restrict__ A, const float* __restrict__ W,
        const float* __restrict__ bias, float* __restrict__ C,
        int M, int N, int K, int act)
{
    __shared__ float As[16][128];
    __shared__ float Ws[16][128];

    int tid  = threadIdx.x;
    int tx   = tid & 15;        // 16 col groups of 8
    int ty   = tid >> 4;        // 16 row groups of 8
    int rowb = blockIdx.y * 128;
    int colb = blockIdx.x * 128;

    int ar = tid >> 1,  ac = (tid & 1) * 8;   // A-tile: 128 rows x 16 k
    int wr = tid >> 4,  wc = (tid & 15) * 8;  // W-tile: 16 k x 128 cols

    const float* Ag = A + (long)(rowb + ar) * K + ac;
    const float* Wg = W + (long)wr * N + colb + wc;

    float acc[8][8];
    #pragma unroll
    for (int i = 0; i < 8; i++)
        #pragma unroll
        for (int j = 0; j < 8; j++) acc[i][j] = 0.0f;

    for (int kt = 0; kt < K; kt += 16) {
        float4 a0 = *(const float4*)(Ag + kt);
        float4 a1 = *(const float4*)(Ag + kt + 4);
        float4 w0 = *(const float4*)(Wg + (long)kt * N);
        float4 w1 = *(const float4*)(Wg + (long)kt * N + 4);

        As[ac + 0][ar] = a0.x; As[ac + 1][ar] = a0.y;
        As[ac + 2][ar] = a0.z; As[ac + 3][ar] = a0.w;
        As[ac + 4][ar] = a1.x; As[ac + 5][ar] = a1.y;
        As[ac + 6][ar] = a1.z; As[ac + 7][ar] = a1.w;
        *(float4*)&Ws[wr][wc]     = w0;
        *(float4*)&Ws[wr][wc + 4] = w1;
        __syncthreads();

        #pragma unroll
        for (int kk = 0; kk < 16; kk++) {
            float4 av0 = *(const float4*)&As[kk][ty * 8];
            float4 av1 = *(const float4*)&As[kk][ty * 8 + 4];
            float4 bv0 = *(const float4*)&Ws[kk][tx * 8];
            float4 bv1 = *(const float4*)&Ws[kk][tx * 8 + 4];
            float av[8] = {av0.x, av0.y, av0.z, av0.w, av1.x, av1.y, av1.z, av1.w};
            float bv[8] = {bv0.x, bv0.y, bv0.z, bv0.w, bv1.x, bv1.y, bv1.z, bv1.w};
            #pragma unroll
            for (int i = 0; i < 8; i++)
                #pragma unroll
                for (int j = 0; j < 8; j++)
                    acc[i][j] += av[i] * bv[j];
        }
        __syncthreads();
    }

    float bb[8];
    #pragma unroll
    for (int j = 0; j < 8; j++) bb[j] = bias[colb + tx * 8 + j];

    #pragma unroll
    for (int i = 0; i < 8; i++) {
        float o[8];
        #pragma unroll
        for (int j = 0; j < 8; j++) {
            float c = acc[i][j] + bb[j];
            o[j] = act ? gelu_exact(c) : c;
        }
        long base = (long)(rowb + ty * 8 + i) * N + colb + tx * 8;
        *(float4*)&C[base]     = make_float4(o[0], o[1], o[2], o[3]);
        *(float4*)&C[base + 4] = make_float4(o[4], o[5], o[6], o[7]);
    }
}

// ---------------- kernel 3: attention, one block per (b,h) ----------------
// smem: Q[256][64], Kt[64][260] (padded), V[256][64], per-warp probs [16][256], bias[256]
#define KTP 260
#define ATTN_SMEM_BYTES ((Ss*DHh + DHh*KTP + Ss*DHh + 16*Ss + Ss) * 4)

__global__ void __launch_bounds__(512) attn_kernel(
        const float* __restrict__ q, const float* __restrict__ k,
        const float* __restrict__ v, const int* __restrict__ ids,
        float* __restrict__ ctx)
{
    extern __shared__ float sm[];
    float* sQ    = sm;                      // 256*64
    float* sKt   = sQ  + Ss * DHh;          // 64*260
    float* sV    = sKt + DHh * KTP;         // 256*64
    float* sP    = sV  + Ss * DHh;          // 16*256
    float* sBias = sP  + 16 * Ss;           // 256

    int b = blockIdx.x >> 2;
    int h = blockIdx.x & 3;
    int base = b * Ss;
    int hoff = h * DHh;
    int tid = threadIdx.x;

    for (int idx = tid; idx < Ss * DHh; idx += 512) {
        int r = idx >> 6, d = idx & 63;
        long g = (long)(base + r) * Dd + hoff + d;
        sQ[idx] = q[g];
        sKt[d * KTP + r] = k[g];
        sV[idx] = v[g];
    }
    if (tid < Ss) sBias[tid] = (ids[base + tid] > 0) ? 0.0f : -10000.0f;
    __syncthreads();

    int w = tid >> 5, l = tid & 31;
    const float scale = 0.125f;   // 1/sqrt(64)

    for (int qi = w; qi < Ss; qi += 16) {
        // ---- scores: lane handles keys {4l..4l+3, 128+4l..128+4l+3} ----
        float a0 = 0, a1 = 0, a2 = 0, a3 = 0, a4 = 0, a5 = 0, a6 = 0, a7 = 0;
        #pragma unroll 4
        for (int d = 0; d < DHh; d++) {
            float qd = sQ[qi * 64 + d];
            float4 k0 = *(const float4*)&sKt[d * KTP + 4 * l];
            float4 k1 = *(const float4*)&sKt[d * KTP + 128 + 4 * l];
            a0 += qd * k0.x; a1 += qd * k0.y; a2 += qd * k0.z; a3 += qd * k0.w;
            a4 += qd * k1.x; a5 += qd * k1.y; a6 += qd * k1.z; a7 += qd * k1.w;
        }
        float sc[8] = {a0, a1, a2, a3, a4, a5, a6, a7};
        float m = -1e30f;
        #pragma unroll
        for (int i = 0; i < 8; i++) {
            int j = (i < 4) ? (4 * l + i) : (128 + 4 * l + (i - 4));
            float bb = (j <= qi) ? sBias[j] : -10000.0f;   // pad AND causal, -1e4 once
            sc[i] = sc[i] * scale + bb;
            m = fmaxf(m, sc[i]);
        }
        #pragma unroll
        for (int o = 16; o > 0; o >>= 1)
            m = fmaxf(m, __shfl_xor_sync(0xffffffffu, m, o));
        float sum = 0.0f;
        #pragma unroll
        for (int i = 0; i < 8; i++) { sc[i] = expf(sc[i] - m); sum += sc[i]; }
        #pragma unroll
        for (int o = 16; o > 0; o >>= 1)
            sum += __shfl_xor_sync(0xffffffffu, sum, o);
        float inv = 1.0f / sum;
        #pragma unroll
        for (int i = 0; i < 8; i++) {
            int j = (i < 4) ? (4 * l + i) : (128 + 4 * l + (i - 4));
            sP[w * Ss + j] = sc[i] * inv;
        }
        __syncwarp();

        // ---- ctx: lane computes output dims 2l, 2l+1 ----
        float c0 = 0.0f, c1 = 0.0f;
        #pragma unroll 4
        for (int j = 0; j < Ss; j++) {
            float pj = sP[w * Ss + j];
            float2 vv = *(const float2*)&sV[j * 64 + 2 * l];
            c0 += pj * vv.x; c1 += pj * vv.y;
        }
        long orow = (long)(base + qi) * Dd + hoff + 2 * l;
        ctx[orow]     = c0;
        ctx[orow + 1] = c1;
        __syncwarp();  // protect sP before next iteration's writes
    }
}

// ---------------- kernel 4: h = LN(t + x) ----------------
__global__ void __launch_bounds__(256) add_ln_kernel(
        const float* __restrict__ a, const float* __restrict__ bres,
        float* __restrict__ out)
{
    long i = (long)blockIdx.x * Dd + threadIdx.x;
    float v = a[i] + bres[i];
    float2 st = rowStats256(v);
    out[i] = (v - st.x) * st.y;
}

// ---------------- kernel 5: x = LN(f2); total += x ----------------
__global__ void __launch_bounds__(256) ln_acc_kernel(
        const float* __restrict__ f2, float* __restrict__ x,
        float* __restrict__ out)
{
    long i = (long)blockIdx.x * Dd + threadIdx.x;
    float v = f2[i];
    float2 st = rowStats256(v);
    float y = (v - st.x) * st.y;
    x[i] = y;
    out[i] += y;
}

// ---------------- launch ----------------
extern "C" void kernel_launch(void* const* d_in, const int* in_sizes, int n_in,
                              void* d_out, int out_size)
{
    const int*   ids      = (const int*)  d_in[0];
    const float* item_emb = (const float*)d_in[1];
    const float* pos_emb  = (const float*)d_in[2];
    const float* Wq = (const float*)d_in[3];  const float* bq = (const float*)d_in[4];
    const float* Wk = (const float*)d_in[5];  const float* bk = (const float*)d_in[6];
    const float* Wv = (const float*)d_in[7];  const float* bv = (const float*)d_in[8];
    const float* Wo = (const float*)d_in[9];  const float* bo = (const float*)d_in[10];
    const float* W1 = (const float*)d_in[11]; const float* b1 = (const float*)d_in[12];
    const float* W2 = (const float*)d_in[13]; const float* b2 = (const float*)d_in[14];
    float* out = (float*)d_out;

    float *x, *q, *k, *v, *ctx, *t, *h, *f1, *f2;
    cudaGetSymbolAddress((void**)&x,   g_x);
    cudaGetSymbolAddress((void**)&q,   g_q);
    cudaGetSymbolAddress((void**)&k,   g_k);
    cudaGetSymbolAddress((void**)&v,   g_v);
    cudaGetSymbolAddress((void**)&ctx, g_ctx);
    cudaGetSymbolAddress((void**)&t,   g_t);
    cudaGetSymbolAddress((void**)&h,   g_h);
    cudaGetSymbolAddress((void**)&f1,  g_f1);
    cudaGetSymbolAddress((void**)&f2,  g_f2);

    cudaFuncSetAttribute(attn_kernel,
                         cudaFuncAttributeMaxDynamicSharedMemorySize,
                         ATTN_SMEM_BYTES);

    embed_ln_kernel<<<NROWS, 256>>>(ids, item_emb, pos_emb, x, out);

    dim3 gD(Dd / 128, NROWS / 128);     // (2, 512) for N=256
    dim3 gF(FF / 128, NROWS / 128);     // (8, 512) for N=1024

    for (int l = 0; l < Ll; l++) {
        const float* wq = Wq + (long)l * Dd * Dd;
        const float* wk = Wk + (long)l * Dd * Dd;
        const float* wv = Wv + (long)l * Dd * Dd;
        const float* wo = Wo + (long)l * Dd * Dd;
        const float* w1 = W1 + (long)l * Dd * FF;
        const float* w2 = W2 + (long)l * FF * Dd;

        gemm_bias_kernel<<<gD, 256>>>(x, wq, bq + l * Dd, q, NROWS, Dd, Dd, 0);
        gemm_bias_kernel<<<gD, 256>>>(x, wk, bk + l * Dd, k, NROWS, Dd, Dd, 0);
        gemm_bias_kernel<<<gD, 256>>>(x, wv, bv + l * Dd, v, NROWS, Dd, Dd, 0);

        attn_kernel<<<Bb * Hh, 512, ATTN_SMEM_BYTES>>>(q, k, v, ids, ctx);

        gemm_bias_kernel<<<gD, 256>>>(ctx, wo, bo + l * Dd, t, NROWS, Dd, Dd, 0);
        add_ln_kernel<<<NROWS, 256>>>(t, x, h);

        gemm_bias_kernel<<<gF, 256>>>(h,  w1, b1 + l * FF, f1, NROWS, FF, Dd, 1);
        gemm_bias_kernel<<<gD, 256>>>(f1, w2, b2 + l * Dd, f2, NROWS, Dd, FF, 0);

        ln_acc_kernel<<<NROWS, 256>>>(f2, x, out);
    }
}

// round 2
// speedup vs baseline: 2.1020x; 2.1020x over previous
#include <cuda_runtime.h>
#include <math.h>
#include <stdint.h>

// ---------------- problem constants ----------------
#define Bb   256
#define Ss   256
#define Dd   256
#define Hh   4
#define DHh  64
#define Ll   2
#define FF   1024               // 4*D
#define NROWS (Bb*Ss)           // 65536

// ---------------- scratch (__device__ globals; no allocation) ----------------
__device__ float g_x  [NROWS*Dd];
__device__ float g_q  [NROWS*Dd];
__device__ float g_k  [NROWS*Dd];
__device__ float g_v  [NROWS*Dd];
__device__ float g_ctx[NROWS*Dd];
__device__ float g_t  [NROWS*Dd];
__device__ float g_h  [NROWS*Dd];
__device__ float g_f1 [NROWS*FF];   // doubles as attention P buffer (exactly B*H*S*S)
__device__ float g_f2 [NROWS*Dd];

// ---------------- helpers ----------------
__device__ __forceinline__ float gelu_exact(float x) {
    return 0.5f * x * (1.0f + erff(x * 0.70710678118654752440f));
}

__device__ __forceinline__ float tf32r(float x) {
    uint32_t u;
    asm("cvt.rna.tf32.f32 %0, %1;" : "=r"(u) : "f"(x));
    return __uint_as_float(u);
}

__device__ __forceinline__ void mma_tf32(float* d, const uint32_t* a, const uint32_t* b) {
    asm volatile(
        "mma.sync.aligned.m16n8k8.row.col.f32.tf32.tf32.f32 "
        "{%0,%1,%2,%3}, {%4,%5,%6,%7}, {%8,%9}, {%0,%1,%2,%3};"
        : "+f"(d[0]), "+f"(d[1]), "+f"(d[2]), "+f"(d[3])
        : "r"(a[0]), "r"(a[1]), "r"(a[2]), "r"(a[3]), "r"(b[0]), "r"(b[1]));
}

// mean + rstd over a 256-wide row, one block of 256 threads
__device__ __forceinline__ float2 rowStats256(float v) {
    float s = v, s2 = v * v;
    #pragma unroll
    for (int o = 16; o > 0; o >>= 1) {
        s  += __shfl_down_sync(0xffffffffu, s,  o);
        s2 += __shfl_down_sync(0xffffffffu, s2, o);
    }
    __shared__ float sh[8], sh2[8];
    int lane = threadIdx.x & 31, wid = threadIdx.x >> 5;
    if (lane == 0) { sh[wid] = s; sh2[wid] = s2; }
    __syncthreads();
    if (threadIdx.x < 32) {
        s  = (lane < 8) ? sh[lane]  : 0.0f;
        s2 = (lane < 8) ? sh2[lane] : 0.0f;
        #pragma unroll
        for (int o = 4; o > 0; o >>= 1) {
            s  += __shfl_down_sync(0xffffffffu, s,  o);
            s2 += __shfl_down_sync(0xffffffffu, s2, o);
        }
        if (lane == 0) { sh[0] = s; sh2[0] = s2; }
    }
    __syncthreads();
    float mu  = sh[0] * (1.0f / 256.0f);
    float var = sh2[0] * (1.0f / 256.0f) - mu * mu;
    return make_float2(mu, rsqrtf(var + 1e-5f));
}

// ---------------- kernel 1: embedding + LN (also init total) ----------------
__global__ void __launch_bounds__(256) embed_ln_kernel(
        const int* __restrict__ ids,
        const float* __restrict__ item_emb,
        const float* __restrict__ pos_emb,
        float* __restrict__ x, float* __restrict__ out)
{
    int row = blockIdx.x;
    int t   = threadIdx.x;
    int s   = row & (Ss - 1);
    int id  = ids[row];
    float v = item_emb[(long)id * Dd + t] + pos_emb[s * Dd + t];
    float2 st = rowStats256(v);
    float y = (v - st.x) * st.y;
    long o = (long)row * Dd + t;
    x[o] = y;
    out[o] = y;   // total = x0
}

// ---------------- kernel 2: tf32 tensor-core GEMM, C = A@W + bias (+GELU) ---
// BM=BN=128, BK=32, 256 threads (8 warps, 4m x 2n), warp tile 32x64.
#define GBK 32
#define ATS 136   // smem stride for Ats[k][m] (128 + 8 pad)
#define BTS 136   // smem stride for Bs[k][n]

__global__ void __launch_bounds__(256, 2) gemm_tf32_kernel(
        const float* __restrict__ A, const float* __restrict__ W,
        const float* __restrict__ bias, float* __restrict__ C,
        int M, int N, int K, int act)
{
    __shared__ float Ats[GBK][ATS];
    __shared__ float Bs [GBK][BTS];

    int tid  = threadIdx.x;
    int w    = tid >> 5, lane = tid & 31;
    int g    = lane >> 2, tig = lane & 3;
    int wm   = w >> 1,  wn = w & 1;
    int rowb = blockIdx.y * 128;
    int colb = blockIdx.x * 128;

    // loader indices
    int am  = tid >> 1;            // 0..127 (m row)
    int akq = (tid & 1) * 16;      // k sub-offset 0/16
    int bk  = tid >> 3;            // 0..31 (k row)
    int bnq = tid & 7;             // 0..7

    const float* Ag = A + (long)(rowb + am) * K + akq;
    const float* Wg = W + (long)bk * N + colb;

    float acc[2][8][4];
    #pragma unroll
    for (int mt = 0; mt < 2; mt++)
        #pragma unroll
        for (int nt = 0; nt < 8; nt++)
            #pragma unroll
            for (int r = 0; r < 4; r++) acc[mt][nt][r] = 0.0f;

    for (int kt = 0; kt < K; kt += GBK) {
        __syncthreads();
        // --- stage A (transposed, tf32-rounded) ---
        #pragma unroll
        for (int i = 0; i < 4; i++) {
            float4 v = *(const float4*)(Ag + kt + 4 * i);
            Ats[akq + 4*i + 0][am] = tf32r(v.x);
            Ats[akq + 4*i + 1][am] = tf32r(v.y);
            Ats[akq + 4*i + 2][am] = tf32r(v.z);
            Ats[akq + 4*i + 3][am] = tf32r(v.w);
        }
        // --- stage B (tf32-rounded) ---
        #pragma unroll
        for (int i = 0; i < 4; i++) {
            float4 v = *(const float4*)(Wg + (long)kt * N + 4 * (bnq + 8 * i));
            float4 r = make_float4(tf32r(v.x), tf32r(v.y), tf32r(v.z), tf32r(v.w));
            *(float4*)&Bs[bk][4 * (bnq + 8 * i)] = r;
        }
        __syncthreads();

        #pragma unroll
        for (int ks = 0; ks < 4; ks++) {
            int k0 = ks * 8;
            uint32_t a[2][4], b[8][2];
            #pragma unroll
            for (int mt = 0; mt < 2; mt++) {
                int mb = wm * 32 + mt * 16 + g;
                a[mt][0] = __float_as_uint(Ats[k0 + tig    ][mb    ]);
                a[mt][1] = __float_as_uint(Ats[k0 + tig    ][mb + 8]);
                a[mt][2] = __float_as_uint(Ats[k0 + 4 + tig][mb    ]);
                a[mt][3] = __float_as_uint(Ats[k0 + 4 + tig][mb + 8]);
            }
            #pragma unroll
            for (int nt = 0; nt < 8; nt++) {
                int nb = wn * 64 + nt * 8 + g;
                b[nt][0] = __float_as_uint(Bs[k0 + tig    ][nb]);
                b[nt][1] = __float_as_uint(Bs[k0 + 4 + tig][nb]);
            }
            #pragma unroll
            for (int mt = 0; mt < 2; mt++)
                #pragma unroll
                for (int nt = 0; nt < 8; nt++)
                    mma_tf32(acc[mt][nt], a[mt], b[nt]);
        }
    }

    // --- epilogue: bias (+gelu), fp32 stores ---
    #pragma unroll
    for (int mt = 0; mt < 2; mt++) {
        int row0 = rowb + wm * 32 + mt * 16 + g;
        #pragma unroll
        for (int nt = 0; nt < 8; nt++) {
            int col = colb + wn * 64 + nt * 8 + 2 * tig;
            float b0 = bias[col], b1 = bias[col + 1];
            float o0 = acc[mt][nt][0] + b0;
            float o1 = acc[mt][nt][1] + b1;
            float o2 = acc[mt][nt][2] + b0;
            float o3 = acc[mt][nt][3] + b1;
            if (act) { o0 = gelu_exact(o0); o1 = gelu_exact(o1);
                       o2 = gelu_exact(o2); o3 = gelu_exact(o3); }
            *(float2*)&C[(long)row0 * N + col]       = make_float2(o0, o1);
            *(float2*)&C[(long)(row0 + 8) * N + col] = make_float2(o2, o3);
        }
    }
}

// ---------------- kernel 3a: attention scores + softmax -> P (gmem) --------
// block per (b,h); 512 threads (16 warps); each warp 8 q-rows per pass, 2 passes.
#define AKTP 260
#define ATTN_A_SMEM ((64*AKTP + Ss*DHh + Ss) * 4)

__global__ void __launch_bounds__(512) attn_scores_kernel(
        const float* __restrict__ q, const float* __restrict__ k,
        const int* __restrict__ ids, float* __restrict__ P)
{
    extern __shared__ float sm[];
    float* sKt   = sm;                    // 64 x 260
    float* sQ    = sKt + 64 * AKTP;       // 256 x 64
    float* sBias = sQ + Ss * DHh;         // 256

    int bh = blockIdx.x;
    int b = bh >> 2, h = bh & 3;
    int base = b * Ss, hoff = h * DHh;
    int tid = threadIdx.x;

    for (int idx = tid; idx < Ss * DHh; idx += 512) {
        int r = idx >> 6, d = idx & 63;
        long gi = (long)(base + r) * Dd + hoff + d;
        sQ[idx] = q[gi];
        sKt[d * AKTP + r] = k[gi];
    }
    if (tid < Ss) sBias[tid] = (ids[base + tid] > 0) ? 0.0f : -10000.0f;
    __syncthreads();

    int w = tid >> 5, l = tid & 31;
    const float scale = 0.125f;
    float* Pb = P + (long)bh * (Ss * Ss);

    for (int pass = 0; pass < 2; pass++) {
        int q0 = pass * 128 + w * 8;
        float acc[8][8];
        #pragma unroll
        for (int i = 0; i < 8; i++)
            #pragma unroll
            for (int j = 0; j < 8; j++) acc[i][j] = 0.0f;

        #pragma unroll 2
        for (int d = 0; d < DHh; d++) {
            const float* kr = &sKt[d * AKTP];
            float4 k0 = *(const float4*)&kr[4 * l];
            float4 k1 = *(const float4*)&kr[128 + 4 * l];
            #pragma unroll
            for (int i = 0; i < 8; i++) {
                float qd = sQ[(q0 + i) * 64 + d];
                acc[i][0] = fmaf(qd, k0.x, acc[i][0]);
                acc[i][1] = fmaf(qd, k0.y, acc[i][1]);
                acc[i][2] = fmaf(qd, k0.z, acc[i][2]);
                acc[i][3] = fmaf(qd, k0.w, acc[i][3]);
                acc[i][4] = fmaf(qd, k1.x, acc[i][4]);
                acc[i][5] = fmaf(qd, k1.y, acc[i][5]);
                acc[i][6] = fmaf(qd, k1.z, acc[i][6]);
                acc[i][7] = fmaf(qd, k1.w, acc[i][7]);
            }
        }

        #pragma unroll
        for (int i = 0; i < 8; i++) {
            int qi = q0 + i;
            float sc[8];
            #pragma unroll
            for (int jj = 0; jj < 4; jj++) {
                int ja = 4 * l + jj;
                int jb = 128 + 4 * l + jj;
                sc[jj]     = acc[i][jj]     * scale + ((ja <= qi) ? sBias[ja] : -10000.0f);
                sc[4 + jj] = acc[i][4 + jj] * scale + ((jb <= qi) ? sBias[jb] : -10000.0f);
            }
            float m = sc[0];
            #pragma unroll
            for (int jj = 1; jj < 8; jj++) m = fmaxf(m, sc[jj]);
            #pragma unroll
            for (int o = 16; o > 0; o >>= 1)
                m = fmaxf(m, __shfl_xor_sync(0xffffffffu, m, o));
            float s = 0.0f;
            #pragma unroll
            for (int jj = 0; jj < 8; jj++) { sc[jj] = __expf(sc[jj] - m); s += sc[jj]; }
            #pragma unroll
            for (int o = 16; o > 0; o >>= 1)
                s += __shfl_xor_sync(0xffffffffu, s, o);
            float inv = 1.0f / s;
            *(float4*)&Pb[(long)qi * Ss + 4 * l] =
                make_float4(sc[0]*inv, sc[1]*inv, sc[2]*inv, sc[3]*inv);
            *(float4*)&Pb[(long)qi * Ss + 128 + 4 * l] =
                make_float4(sc[4]*inv, sc[5]*inv, sc[6]*inv, sc[7]*inv);
        }
    }
}

// ---------------- kernel 3b: ctx = P @ V ------------------------------------
// block per (b,h); 256 threads (8 warps). Warp = 32 q-rows (lane-per-row) x 32 dims.
#define SPS 257
#define ATTN_B_SMEM ((Ss*DHh + 128*SPS) * 4)

__global__ void __launch_bounds__(256) attn_ctx_kernel(
        const float* __restrict__ P, const float* __restrict__ v,
        float* __restrict__ ctx)
{
    extern __shared__ float sm[];
    float* sV = sm;               // 256 x 64
    float* sP = sV + Ss * DHh;    // 128 x 257

    int bh = blockIdx.x;
    int b = bh >> 2, h = bh & 3;
    int base = b * Ss, hoff = h * DHh;
    int tid = threadIdx.x;
    int w = tid >> 5, l = tid & 31;
    int qg = w >> 1;              // 0..3 : q-group within 128-chunk
    int dg = (w & 1) * 32;        // d-offset 0 or 32

    for (int idx = tid; idx < Ss * DHh; idx += 256) {
        int r = idx >> 6, d = idx & 63;
        sV[idx] = v[(long)(base + r) * Dd + hoff + d];
    }

    const float* Pb = P + (long)bh * (Ss * Ss);

    for (int c = 0; c < 2; c++) {
        __syncthreads();
        // stage P rows [c*128, c*128+128) into sP (stride 257)
        for (int idx = tid; idx < 128 * 64; idx += 256) {
            int flat = idx * 4;
            int r = flat >> 8, col = flat & 255;
            float4 pv = *(const float4*)(Pb + (long)(c * 128 + r) * Ss + col);
            float* d0 = &sP[r * SPS + col];
            d0[0] = pv.x; d0[1] = pv.y; d0[2] = pv.z; d0[3] = pv.w;
        }
        __syncthreads();

        int lr = qg * 32 + l;     // local q row within chunk
        float acc[32];
        #pragma unroll
        for (int i = 0; i < 32; i++) acc[i] = 0.0f;

        #pragma unroll 2
        for (int j = 0; j < Ss; j++) {
            float p = sP[lr * SPS + j];
            const float* vr = &sV[j * 64 + dg];
            #pragma unroll
            for (int dd = 0; dd < 8; dd++) {
                float4 vb = *(const float4*)&vr[dd * 4];
                acc[dd*4+0] = fmaf(p, vb.x, acc[dd*4+0]);
                acc[dd*4+1] = fmaf(p, vb.y, acc[dd*4+1]);
                acc[dd*4+2] = fmaf(p, vb.z, acc[dd*4+2]);
                acc[dd*4+3] = fmaf(p, vb.w, acc[dd*4+3]);
            }
        }

        float* outp = ctx + (long)(base + c * 128 + lr) * Dd + hoff + dg;
        #pragma unroll
        for (int dd = 0; dd < 8; dd++)
            *(float4*)&outp[dd * 4] =
                make_float4(acc[dd*4], acc[dd*4+1], acc[dd*4+2], acc[dd*4+3]);
    }
}

// ---------------- kernel 4: h = LN(t + x) ----------------
__global__ void __launch_bounds__(256) add_ln_kernel(
        const float* __restrict__ a, const float* __restrict__ bres,
        float* __restrict__ out)
{
    long i = (long)blockIdx.x * Dd + threadIdx.x;
    float v = a[i] + bres[i];
    float2 st = rowStats256(v);
    out[i] = (v - st.x) * st.y;
}

// ---------------- kernel 5: x = LN(f2); total += x ----------------
__global__ void __launch_bounds__(256) ln_acc_kernel(
        const float* __restrict__ f2, float* __restrict__ x,
        float* __restrict__ out)
{
    long i = (long)blockIdx.x * Dd + threadIdx.x;
    float v = f2[i];
    float2 st = rowStats256(v);
    float y = (v - st.x) * st.y;
    x[i] = y;
    out[i] += y;
}

// ---------------- launch ----------------
extern "C" void kernel_launch(void* const* d_in, const int* in_sizes, int n_in,
                              void* d_out, int out_size)
{
    const int*   ids      = (const int*)  d_in[0];
    const float* item_emb = (const float*)d_in[1];
    const float* pos_emb  = (const float*)d_in[2];
    const float* Wq = (const float*)d_in[3];  const float* bq = (const float*)d_in[4];
    const float* Wk = (const float*)d_in[5];  const float* bk = (const float*)d_in[6];
    const float* Wv = (const float*)d_in[7];  const float* bv = (const float*)d_in[8];
    const float* Wo = (const float*)d_in[9];  const float* bo = (const float*)d_in[10];
    const float* W1 = (const float*)d_in[11]; const float* b1 = (const float*)d_in[12];
    const float* W2 = (const float*)d_in[13]; const float* b2 = (const float*)d_in[14];
    float* out = (float*)d_out;

    float *x, *q, *k, *v, *ctx, *t, *h, *f1, *f2;
    cudaGetSymbolAddress((void**)&x,   g_x);
    cudaGetSymbolAddress((void**)&q,   g_q);
    cudaGetSymbolAddress((void**)&k,   g_k);
    cudaGetSymbolAddress((void**)&v,   g_v);
    cudaGetSymbolAddress((void**)&ctx, g_ctx);
    cudaGetSymbolAddress((void**)&t,   g_t);
    cudaGetSymbolAddress((void**)&h,   g_h);
    cudaGetSymbolAddress((void**)&f1,  g_f1);
    cudaGetSymbolAddress((void**)&f2,  g_f2);

    cudaFuncSetAttribute(attn_scores_kernel,
                         cudaFuncAttributeMaxDynamicSharedMemorySize, ATTN_A_SMEM);
    cudaFuncSetAttribute(attn_ctx_kernel,
                         cudaFuncAttributeMaxDynamicSharedMemorySize, ATTN_B_SMEM);

    embed_ln_kernel<<<NROWS, 256>>>(ids, item_emb, pos_emb, x, out);

    dim3 gD(Dd / 128, NROWS / 128);     // (2, 512)
    dim3 gF(FF / 128, NROWS / 128);     // (8, 512)

    for (int l = 0; l < Ll; l++) {
        const float* wq = Wq + (long)l * Dd * Dd;
        const float* wk = Wk + (long)l * Dd * Dd;
        const float* wv = Wv + (long)l * Dd * Dd;
        const float* wo = Wo + (long)l * Dd * Dd;
        const float* w1 = W1 + (long)l * Dd * FF;
        const float* w2 = W2 + (long)l * FF * Dd;

        gemm_tf32_kernel<<<gD, 256>>>(x, wq, bq + l * Dd, q, NROWS, Dd, Dd, 0);
        gemm_tf32_kernel<<<gD, 256>>>(x, wk, bk + l * Dd, k, NROWS, Dd, Dd, 0);
        gemm_tf32_kernel<<<gD, 256>>>(x, wv, bv + l * Dd, v, NROWS, Dd, Dd, 0);

        attn_scores_kernel<<<Bb * Hh, 512, ATTN_A_SMEM>>>(q, k, ids, f1);
        attn_ctx_kernel<<<Bb * Hh, 256, ATTN_B_SMEM>>>(f1, v, ctx);

        gemm_tf32_kernel<<<gD, 256>>>(ctx, wo, bo + l * Dd, t, NROWS, Dd, Dd, 0);
        add_ln_kernel<<<NROWS, 256>>>(t, x, h);

        gemm_tf32_kernel<<<gF, 256>>>(h,  w1, b1 + l * FF, f1, NROWS, FF, Dd, 1);
        gemm_tf32_kernel<<<gD, 256>>>(f1, w2, b2 + l * Dd, f2, NROWS, Dd, FF, 0);

        ln_acc_kernel<<<NROWS, 256>>>(f2, x, out);
    }
}

// round 3
// speedup vs baseline: 2.8894x; 1.3746x over previous
#include <cuda_runtime.h>
#include <math.h>
#include <stdint.h>

// ---------------- problem constants ----------------
#define Bb   256
#define Ss   256
#define Dd   256
#define Hh   4
#define DHh  64
#define Ll   2
#define FF   1024               // 4*D
#define NROWS (Bb*Ss)           // 65536

// ---------------- scratch (__device__ globals; no allocation) ----------------
__device__ float g_x  [NROWS*Dd];
__device__ float g_q  [NROWS*Dd];
__device__ float g_k  [NROWS*Dd];
__device__ float g_v  [NROWS*Dd];
__device__ float g_ctx[NROWS*Dd];
__device__ float g_t  [NROWS*Dd];
__device__ float g_h  [NROWS*Dd];
__device__ float g_f1 [NROWS*FF];
__device__ float g_f2 [NROWS*Dd];

// ---------------- helpers ----------------
__device__ __forceinline__ float gelu_exact(float x) {
    return 0.5f * x * (1.0f + erff(x * 0.70710678118654752440f));
}

__device__ __forceinline__ float tf32r(float x) {
    uint32_t u;
    asm("cvt.rna.tf32.f32 %0, %1;" : "=r"(u) : "f"(x));
    return __uint_as_float(u);
}

__device__ __forceinline__ void mma_tf32(float* d, const uint32_t* a, const uint32_t* b) {
    asm volatile(
        "mma.sync.aligned.m16n8k8.row.col.f32.tf32.tf32.f32 "
        "{%0,%1,%2,%3}, {%4,%5,%6,%7}, {%8,%9}, {%0,%1,%2,%3};"
        : "+f"(d[0]), "+f"(d[1]), "+f"(d[2]), "+f"(d[3])
        : "r"(a[0]), "r"(a[1]), "r"(a[2]), "r"(a[3]), "r"(b[0]), "r"(b[1]));
}

// mean + rstd over a 256-wide row, one block of 256 threads
__device__ __forceinline__ float2 rowStats256(float v) {
    float s = v, s2 = v * v;
    #pragma unroll
    for (int o = 16; o > 0; o >>= 1) {
        s  += __shfl_down_sync(0xffffffffu, s,  o);
        s2 += __shfl_down_sync(0xffffffffu, s2, o);
    }
    __shared__ float sh[8], sh2[8];
    int lane = threadIdx.x & 31, wid = threadIdx.x >> 5;
    if (lane == 0) { sh[wid] = s; sh2[wid] = s2; }
    __syncthreads();
    if (threadIdx.x < 32) {
        s  = (lane < 8) ? sh[lane]  : 0.0f;
        s2 = (lane < 8) ? sh2[lane] : 0.0f;
        #pragma unroll
        for (int o = 4; o > 0; o >>= 1) {
            s  += __shfl_down_sync(0xffffffffu, s,  o);
            s2 += __shfl_down_sync(0xffffffffu, s2, o);
        }
        if (lane == 0) { sh[0] = s; sh2[0] = s2; }
    }
    __syncthreads();
    float mu  = sh[0] * (1.0f / 256.0f);
    float var = sh2[0] * (1.0f / 256.0f) - mu * mu;
    return make_float2(mu, rsqrtf(var + 1e-5f));
}

// ---------------- kernel 1: embedding + LN (also init total) ----------------
__global__ void __launch_bounds__(256) embed_ln_kernel(
        const int* __restrict__ ids,
        const float* __restrict__ item_emb,
        const float* __restrict__ pos_emb,
        float* __restrict__ x, float* __restrict__ out)
{
    int row = blockIdx.x;
    int t   = threadIdx.x;
    int s   = row & (Ss - 1);
    int id  = ids[row];
    float v = item_emb[(long)id * Dd + t] + pos_emb[s * Dd + t];
    float2 st = rowStats256(v);
    float y = (v - st.x) * st.y;
    long o = (long)row * Dd + t;
    x[o] = y;
    out[o] = y;   // total = x0
}

// ---------------- kernel 2: tf32 tensor-core GEMM, C = A@W + bias (+GELU) ---
#define GBK 32
#define ATS 136
#define BTS 136

__global__ void __launch_bounds__(256, 2) gemm_tf32_kernel(
        const float* __restrict__ A, const float* __restrict__ W,
        const float* __restrict__ bias, float* __restrict__ C,
        int M, int N, int K, int act)
{
    __shared__ float Ats[GBK][ATS];
    __shared__ float Bs [GBK][BTS];

    int tid  = threadIdx.x;
    int w    = tid >> 5, lane = tid & 31;
    int g    = lane >> 2, tig = lane & 3;
    int wm   = w >> 1,  wn = w & 1;
    int rowb = blockIdx.y * 128;
    int colb = blockIdx.x * 128;

    int am  = tid >> 1;
    int akq = (tid & 1) * 16;
    int bk  = tid >> 3;
    int bnq = tid & 7;

    const float* Ag = A + (long)(rowb + am) * K + akq;
    const float* Wg = W + (long)bk * N + colb;

    float acc[2][8][4];
    #pragma unroll
    for (int mt = 0; mt < 2; mt++)
        #pragma unroll
        for (int nt = 0; nt < 8; nt++)
            #pragma unroll
            for (int r = 0; r < 4; r++) acc[mt][nt][r] = 0.0f;

    for (int kt = 0; kt < K; kt += GBK) {
        __syncthreads();
        #pragma unroll
        for (int i = 0; i < 4; i++) {
            float4 v = *(const float4*)(Ag + kt + 4 * i);
            Ats[akq + 4*i + 0][am] = tf32r(v.x);
            Ats[akq + 4*i + 1][am] = tf32r(v.y);
            Ats[akq + 4*i + 2][am] = tf32r(v.z);
            Ats[akq + 4*i + 3][am] = tf32r(v.w);
        }
        #pragma unroll
        for (int i = 0; i < 4; i++) {
            float4 v = *(const float4*)(Wg + (long)kt * N + 4 * (bnq + 8 * i));
            float4 r = make_float4(tf32r(v.x), tf32r(v.y), tf32r(v.z), tf32r(v.w));
            *(float4*)&Bs[bk][4 * (bnq + 8 * i)] = r;
        }
        __syncthreads();

        #pragma unroll
        for (int ks = 0; ks < 4; ks++) {
            int k0 = ks * 8;
            uint32_t a[2][4], b[8][2];
            #pragma unroll
            for (int mt = 0; mt < 2; mt++) {
                int mb = wm * 32 + mt * 16 + g;
                a[mt][0] = __float_as_uint(Ats[k0 + tig    ][mb    ]);
                a[mt][1] = __float_as_uint(Ats[k0 + tig    ][mb + 8]);
                a[mt][2] = __float_as_uint(Ats[k0 + 4 + tig][mb    ]);
                a[mt][3] = __float_as_uint(Ats[k0 + 4 + tig][mb + 8]);
            }
            #pragma unroll
            for (int nt = 0; nt < 8; nt++) {
                int nb = wn * 64 + nt * 8 + g;
                b[nt][0] = __float_as_uint(Bs[k0 + tig    ][nb]);
                b[nt][1] = __float_as_uint(Bs[k0 + 4 + tig][nb]);
            }
            #pragma unroll
            for (int mt = 0; mt < 2; mt++)
                #pragma unroll
                for (int nt = 0; nt < 8; nt++)
                    mma_tf32(acc[mt][nt], a[mt], b[nt]);
        }
    }

    #pragma unroll
    for (int mt = 0; mt < 2; mt++) {
        int row0 = rowb + wm * 32 + mt * 16 + g;
        #pragma unroll
        for (int nt = 0; nt < 8; nt++) {
            int col = colb + wn * 64 + nt * 8 + 2 * tig;
            float b0 = bias[col], b1 = bias[col + 1];
            float o0 = acc[mt][nt][0] + b0;
            float o1 = acc[mt][nt][1] + b1;
            float o2 = acc[mt][nt][2] + b0;
            float o3 = acc[mt][nt][3] + b1;
            if (act) { o0 = gelu_exact(o0); o1 = gelu_exact(o1);
                       o2 = gelu_exact(o2); o3 = gelu_exact(o3); }
            *(float2*)&C[(long)row0 * N + col]       = make_float2(o0, o1);
            *(float2*)&C[(long)(row0 + 8) * N + col] = make_float2(o2, o3);
        }
    }
}

// ---------------- kernel 3: FUSED tensor-core attention ---------------------
// One block per (b,h); 256 threads (8 warps). Each warp: 16 q-rows per pass,
// 2 passes (128 rows/pass). Full key range per warp -> softmax stays in-warp.
// smem strides chosen for conflict-free fragment reads:
//   Qs[256][68]  : (68g+tig)%32  = 4g+tig   -> 32 distinct
//   Ks[64][264]  : (264tig+g)%32 = 8tig+g   -> 32 distinct
//   Vs[256][72]  : (72tig+g)%32  = 8tig+g   -> 32 distinct
#define QS 68
#define KS 264
#define VS 72
#define ATTN_SMEM ((Ss*QS + DHh*KS + Ss*VS + Ss) * 4)

__global__ void __launch_bounds__(256, 1) attn_fused_kernel(
        const float* __restrict__ q, const float* __restrict__ k,
        const float* __restrict__ v, const int* __restrict__ ids,
        float* __restrict__ ctx)
{
    extern __shared__ float sm[];
    float* sQ    = sm;                 // 256 x 68
    float* sKt   = sQ  + Ss * QS;      // 64  x 264   (Kt[d][key])
    float* sV    = sKt + DHh * KS;     // 256 x 72    (V[key][d])
    float* sBias = sV  + Ss * VS;      // 256

    int bh = blockIdx.x;
    int b = bh >> 2, h = bh & 3;
    int base = b * Ss, hoff = h * DHh;
    int tid = threadIdx.x;

    // ---- stage Q, Kt, V (tf32-rounded) ----
    for (int idx = tid; idx < Ss * (DHh / 4); idx += 256) {
        int r = idx >> 4, d4 = (idx & 15) * 4;
        long gi = (long)(base + r) * Dd + hoff + d4;
        float4 qv = *(const float4*)(q + gi);
        float4 kv = *(const float4*)(k + gi);
        float4 vv = *(const float4*)(v + gi);
        float* qd = &sQ[r * QS + d4];
        qd[0] = tf32r(qv.x); qd[1] = tf32r(qv.y);
        qd[2] = tf32r(qv.z); qd[3] = tf32r(qv.w);
        sKt[(d4    ) * KS + r] = tf32r(kv.x);
        sKt[(d4 + 1) * KS + r] = tf32r(kv.y);
        sKt[(d4 + 2) * KS + r] = tf32r(kv.z);
        sKt[(d4 + 3) * KS + r] = tf32r(kv.w);
        float* vd = &sV[r * VS + d4];
        vd[0] = tf32r(vv.x); vd[1] = tf32r(vv.y);
        vd[2] = tf32r(vv.z); vd[3] = tf32r(vv.w);
    }
    if (tid < Ss) sBias[tid] = (ids[base + tid] > 0) ? 0.0f : -10000.0f;
    __syncthreads();

    int w = tid >> 5, lane = tid & 31;
    int g = lane >> 2, tig = lane & 3;
    int laneBase = lane & ~3;
    const float scale = 0.125f;

    for (int pass = 0; pass < 2; pass++) {
        int m0 = pass * 128 + w * 16;
        int r0 = m0 + g;           // query row (this lane, lower half)
        int r1 = m0 + 8 + g;       // upper half

        // ---- S = Q @ K^T : acc[nt] covers cols nt*8..nt*8+7 ----
        float acc[32][4];
        #pragma unroll
        for (int nt = 0; nt < 32; nt++)
            #pragma unroll
            for (int r = 0; r < 4; r++) acc[nt][r] = 0.0f;

        #pragma unroll
        for (int kc = 0; kc < 8; kc++) {
            int k0 = kc * 8;
            uint32_t a[4];
            a[0] = __float_as_uint(sQ[r0 * QS + k0 + tig]);
            a[1] = __float_as_uint(sQ[r1 * QS + k0 + tig]);
            a[2] = __float_as_uint(sQ[r0 * QS + k0 + 4 + tig]);
            a[3] = __float_as_uint(sQ[r1 * QS + k0 + 4 + tig]);
            #pragma unroll
            for (int nt = 0; nt < 32; nt++) {
                uint32_t bfr[2];
                bfr[0] = __float_as_uint(sKt[(k0 + tig    ) * KS + nt * 8 + g]);
                bfr[1] = __float_as_uint(sKt[(k0 + 4 + tig) * KS + nt * 8 + g]);
                mma_tf32(acc[nt], a, bfr);
            }
        }

        // ---- softmax (rows r0, r1) ----
        float mx0 = -1e30f, mx1 = -1e30f;
        #pragma unroll
        for (int nt = 0; nt < 32; nt++) {
            int c0 = nt * 8 + 2 * tig, c1 = c0 + 1;
            float bp0 = sBias[c0], bp1 = sBias[c1];
            float b00 = (c0 <= r0) ? bp0 : -10000.0f;
            float b10 = (c1 <= r0) ? bp1 : -10000.0f;
            float b01 = (c0 <= r1) ? bp0 : -10000.0f;
            float b11 = (c1 <= r1) ? bp1 : -10000.0f;
            acc[nt][0] = acc[nt][0] * scale + b00;
            acc[nt][1] = acc[nt][1] * scale + b10;
            acc[nt][2] = acc[nt][2] * scale + b01;
            acc[nt][3] = acc[nt][3] * scale + b11;
            mx0 = fmaxf(mx0, fmaxf(acc[nt][0], acc[nt][1]));
            mx1 = fmaxf(mx1, fmaxf(acc[nt][2], acc[nt][3]));
        }
        mx0 = fmaxf(mx0, __shfl_xor_sync(0xffffffffu, mx0, 1));
        mx0 = fmaxf(mx0, __shfl_xor_sync(0xffffffffu, mx0, 2));
        mx1 = fmaxf(mx1, __shfl_xor_sync(0xffffffffu, mx1, 1));
        mx1 = fmaxf(mx1, __shfl_xor_sync(0xffffffffu, mx1, 2));

        float s0 = 0.0f, s1 = 0.0f;
        #pragma unroll
        for (int nt = 0; nt < 32; nt++) {
            acc[nt][0] = __expf(acc[nt][0] - mx0);
            acc[nt][1] = __expf(acc[nt][1] - mx0);
            acc[nt][2] = __expf(acc[nt][2] - mx1);
            acc[nt][3] = __expf(acc[nt][3] - mx1);
            s0 += acc[nt][0] + acc[nt][1];
            s1 += acc[nt][2] + acc[nt][3];
        }
        s0 += __shfl_xor_sync(0xffffffffu, s0, 1);
        s0 += __shfl_xor_sync(0xffffffffu, s0, 2);
        s1 += __shfl_xor_sync(0xffffffffu, s1, 1);
        s1 += __shfl_xor_sync(0xffffffffu, s1, 2);
        float i0 = 1.0f / s0, i1 = 1.0f / s1;
        #pragma unroll
        for (int nt = 0; nt < 32; nt++) {
            acc[nt][0] = tf32r(acc[nt][0] * i0);
            acc[nt][1] = tf32r(acc[nt][1] * i0);
            acc[nt][2] = tf32r(acc[nt][2] * i1);
            acc[nt][3] = tf32r(acc[nt][3] * i1);
        }

        // ---- ctx = P @ V ----
        // remap acc (cols 2tig,2tig+1) -> A-frag (cols tig, tig+4) via shfl
        float acc2[8][4];
        #pragma unroll
        for (int nt = 0; nt < 8; nt++)
            #pragma unroll
            for (int r = 0; r < 4; r++) acc2[nt][r] = 0.0f;

        int srcA = laneBase | (tig >> 1);
        int srcC = laneBase | ((tig >> 1) + 2);
        bool odd = (tig & 1);

        #pragma unroll
        for (int kc = 0; kc < 32; kc++) {
            float x0 = __shfl_sync(0xffffffffu, acc[kc][0], srcA);
            float x1 = __shfl_sync(0xffffffffu, acc[kc][1], srcA);
            float y0 = __shfl_sync(0xffffffffu, acc[kc][2], srcA);
            float y1 = __shfl_sync(0xffffffffu, acc[kc][3], srcA);
            float z0 = __shfl_sync(0xffffffffu, acc[kc][0], srcC);
            float z1 = __shfl_sync(0xffffffffu, acc[kc][1], srcC);
            float u0 = __shfl_sync(0xffffffffu, acc[kc][2], srcC);
            float u1 = __shfl_sync(0xffffffffu, acc[kc][3], srcC);
            uint32_t a[4];
            a[0] = __float_as_uint(odd ? x1 : x0);   // (r0, col tig)
            a[1] = __float_as_uint(odd ? y1 : y0);   // (r1, col tig)
            a[2] = __float_as_uint(odd ? z1 : z0);   // (r0, col tig+4)
            a[3] = __float_as_uint(odd ? u1 : u0);   // (r1, col tig+4)
            int kk = kc * 8;
            #pragma unroll
            for (int nt = 0; nt < 8; nt++) {
                uint32_t bfr[2];
                bfr[0] = __float_as_uint(sV[(kk + tig    ) * VS + nt * 8 + g]);
                bfr[1] = __float_as_uint(sV[(kk + 4 + tig) * VS + nt * 8 + g]);
                mma_tf32(acc2[nt], a, bfr);
            }
        }

        // ---- store ctx ----
        long o0 = (long)(base + r0) * Dd + hoff;
        long o1 = (long)(base + r1) * Dd + hoff;
        #pragma unroll
        for (int nt = 0; nt < 8; nt++) {
            int d = nt * 8 + 2 * tig;
            *(float2*)&ctx[o0 + d] = make_float2(acc2[nt][0], acc2[nt][1]);
            *(float2*)&ctx[o1 + d] = make_float2(acc2[nt][2], acc2[nt][3]);
        }
    }
}

// ---------------- kernel 4: h = LN(t + x) ----------------
__global__ void __launch_bounds__(256) add_ln_kernel(
        const float* __restrict__ a, const float* __restrict__ bres,
        float* __restrict__ out)
{
    long i = (long)blockIdx.x * Dd + threadIdx.x;
    float v = a[i] + bres[i];
    float2 st = rowStats256(v);
    out[i] = (v - st.x) * st.y;
}

// ---------------- kernel 5: x = LN(f2); total += x ----------------
__global__ void __launch_bounds__(256) ln_acc_kernel(
        const float* __restrict__ f2, float* __restrict__ x,
        float* __restrict__ out)
{
    long i = (long)blockIdx.x * Dd + threadIdx.x;
    float v = f2[i];
    float2 st = rowStats256(v);
    float y = (v - st.x) * st.y;
    x[i] = y;
    out[i] += y;
}

// ---------------- launch ----------------
extern "C" void kernel_launch(void* const* d_in, const int* in_sizes, int n_in,
                              void* d_out, int out_size)
{
    const int*   ids      = (const int*)  d_in[0];
    const float* item_emb = (const float*)d_in[1];
    const float* pos_emb  = (const float*)d_in[2];
    const float* Wq = (const float*)d_in[3];  const float* bq = (const float*)d_in[4];
    const float* Wk = (const float*)d_in[5];  const float* bk = (const float*)d_in[6];
    const float* Wv = (const float*)d_in[7];  const float* bv = (const float*)d_in[8];
    const float* Wo = (const float*)d_in[9];  const float* bo = (const float*)d_in[10];
    const float* W1 = (const float*)d_in[11]; const float* b1 = (const float*)d_in[12];
    const float* W2 = (const float*)d_in[13]; const float* b2 = (const float*)d_in[14];
    float* out = (float*)d_out;

    float *x, *q, *k, *v, *ctx, *t, *h, *f1, *f2;
    cudaGetSymbolAddress((void**)&x,   g_x);
    cudaGetSymbolAddress((void**)&q,   g_q);
    cudaGetSymbolAddress((void**)&k,   g_k);
    cudaGetSymbolAddress((void**)&v,   g_v);
    cudaGetSymbolAddress((void**)&ctx, g_ctx);
    cudaGetSymbolAddress((void**)&t,   g_t);
    cudaGetSymbolAddress((void**)&h,   g_h);
    cudaGetSymbolAddress((void**)&f1,  g_f1);
    cudaGetSymbolAddress((void**)&f2,  g_f2);

    cudaFuncSetAttribute(attn_fused_kernel,
                         cudaFuncAttributeMaxDynamicSharedMemorySize, ATTN_SMEM);

    embed_ln_kernel<<<NROWS, 256>>>(ids, item_emb, pos_emb, x, out);

    dim3 gD(Dd / 128, NROWS / 128);
    dim3 gF(FF / 128, NROWS / 128);

    for (int l = 0; l < Ll; l++) {
        const float* wq = Wq + (long)l * Dd * Dd;
        const float* wk = Wk + (long)l * Dd * Dd;
        const float* wv = Wv + (long)l * Dd * Dd;
        const float* wo = Wo + (long)l * Dd * Dd;
        const float* w1 = W1 + (long)l * Dd * FF;
        const float* w2 = W2 + (long)l * FF * Dd;

        gemm_tf32_kernel<<<gD, 256>>>(x, wq, bq + l * Dd, q, NROWS, Dd, Dd, 0);
        gemm_tf32_kernel<<<gD, 256>>>(x, wk, bk + l * Dd, k, NROWS, Dd, Dd, 0);
        gemm_tf32_kernel<<<gD, 256>>>(x, wv, bv + l * Dd, v, NROWS, Dd, Dd, 0);

        attn_fused_kernel<<<Bb * Hh, 256, ATTN_SMEM>>>(q, k, v, ids, ctx);

        gemm_tf32_kernel<<<gD, 256>>>(ctx, wo, bo + l * Dd, t, NROWS, Dd, Dd, 0);
        add_ln_kernel<<<NROWS, 256>>>(t, x, h);

        gemm_tf32_kernel<<<gF, 256>>>(h,  w1, b1 + l * FF, f1, NROWS, FF, Dd, 1);
        gemm_tf32_kernel<<<gD, 256>>>(f1, w2, b2 + l * Dd, f2, NROWS, Dd, FF, 0);

        ln_acc_kernel<<<NROWS, 256>>>(f2, x, out);
    }
}

// round 7
// speedup vs baseline: 3.8339x; 1.3269x over previous
#include <cuda_runtime.h>
#include <cuda_fp16.h>
#include <math.h>
#include <stdint.h>

// ---------------- problem constants ----------------
#define Bb   256
#define Ss   256
#define Dd   256
#define Hh   4
#define DHh  64
#define Ll   2
#define FF   1024
#define NROWS (Bb*Ss)           // 65536

// ---------------- scratch (__device__ globals; no allocation) ----------------
__device__ __half g_xh [NROWS*Dd];
__device__ __half g_qkv[NROWS*768];
__device__ __half g_ctx[NROWS*Dd];
__device__ __half g_t  [NROWS*Dd];
__device__ __half g_hh [NROWS*Dd];
__device__ __half g_f1 [NROWS*FF];
__device__ __half g_f2 [NROWS*Dd];
// converted weights (transposed to [N][K], half)
__device__ __half g_wqkvt[Ll*768*Dd];
__device__ __half g_wot  [Ll*Dd*Dd];
__device__ __half g_w1t  [Ll*FF*Dd];
__device__ __half g_w2t  [Ll*Dd*FF];
__device__ float  g_bqkv [Ll*768];

// ---------------- helpers ----------------
__device__ __forceinline__ float gelu_exact(float x) {
    return 0.5f * x * (1.0f + erff(x * 0.70710678118654752440f));
}

__device__ __forceinline__ void mma_f16(float* d, const uint32_t* a, const uint32_t* b) {
    asm volatile(
        "mma.sync.aligned.m16n8k16.row.col.f32.f16.f16.f32 "
        "{%0,%1,%2,%3}, {%4,%5,%6,%7}, {%8,%9}, {%0,%1,%2,%3};"
        : "+f"(d[0]), "+f"(d[1]), "+f"(d[2]), "+f"(d[3])
        : "r"(a[0]), "r"(a[1]), "r"(a[2]), "r"(a[3]), "r"(b[0]), "r"(b[1]));
}

__device__ __forceinline__ uint32_t packh2(float lo, float hi) {
    __half2 h = __floats2half2_rn(lo, hi);
    return *reinterpret_cast<uint32_t*>(&h);
}

// mean + rstd over a 256-wide row, one block of 256 threads
__device__ __forceinline__ float2 rowStats256(float v) {
    float s = v, s2 = v * v;
    #pragma unroll
    for (int o = 16; o > 0; o >>= 1) {
        s  += __shfl_down_sync(0xffffffffu, s,  o);
        s2 += __shfl_down_sync(0xffffffffu, s2, o);
    }
    __shared__ float sh[8], sh2[8];
    int lane = threadIdx.x & 31, wid = threadIdx.x >> 5;
    if (lane == 0) { sh[wid] = s; sh2[wid] = s2; }
    __syncthreads();
    if (threadIdx.x < 32) {
        s  = (lane < 8) ? sh[lane]  : 0.0f;
        s2 = (lane < 8) ? sh2[lane] : 0.0f;
        #pragma unroll
        for (int o = 4; o > 0; o >>= 1) {
            s  += __shfl_down_sync(0xffffffffu, s,  o);
            s2 += __shfl_down_sync(0xffffffffu, s2, o);
        }
        if (lane == 0) { sh[0] = s; sh2[0] = s2; }
    }
    __syncthreads();
    float mu  = sh[0] * (1.0f / 256.0f);
    float var = sh2[0] * (1.0f / 256.0f) - mu * mu;
    return make_float2(mu, rsqrtf(var + 1e-5f));
}

// ---------------- weight transpose+convert: out[n][k] = (half)in[k][n] -------
__global__ void wconv_kernel(const float* __restrict__ in, __half* __restrict__ out,
                             int K, int N)
{
    __shared__ float t[32][33];
    int k0 = blockIdx.y * 32, n0 = blockIdx.x * 32;
    int tx = threadIdx.x, ty = threadIdx.y;
    #pragma unroll
    for (int i = 0; i < 32; i += 8)
        t[ty + i][tx] = in[(long)(k0 + ty + i) * N + n0 + tx];
    __syncthreads();
    #pragma unroll
    for (int i = 0; i < 32; i += 8)
        out[(long)(n0 + ty + i) * K + k0 + tx] = __float2half_rn(t[tx][ty + i]);
}

__global__ void bias_pack_kernel(const float* __restrict__ bq,
                                 const float* __restrict__ bk,
                                 const float* __restrict__ bv,
                                 float* __restrict__ o)
{
    int l = blockIdx.x / 3, t = blockIdx.x % 3, i = threadIdx.x;
    const float* s = (t == 0) ? bq : (t == 1) ? bk : bv;
    o[l * 768 + t * 256 + i] = s[l * 256 + i];
}

// ---------------- kernel 1: embedding + LN (also init total) ----------------
__global__ void __launch_bounds__(256) embed_ln_kernel(
        const int* __restrict__ ids,
        const float* __restrict__ item_emb,
        const float* __restrict__ pos_emb,
        __half* __restrict__ x, float* __restrict__ out)
{
    int row = blockIdx.x;
    int t   = threadIdx.x;
    int s   = row & (Ss - 1);
    int id  = ids[row];
    float v = item_emb[(long)id * Dd + t] + pos_emb[s * Dd + t];
    float2 st = rowStats256(v);
    float y = (v - st.x) * st.y;
    long o = (long)row * Dd + t;
    x[o] = __float2half_rn(y);
    out[o] = y;
}

// ---------------- kernel 2: fp16 GEMM, explicit LDS fragments ---------------
// C(half)[M][N] = A(half)[M][K] @ Wt(half)[N][K]^T + bias(f32), optional GELU.
// BM=BN=128, BK=32, 256 threads (8 warps 4m x 2n), warp tile 32x64.
// Fragments built with plain 32-bit LDS (contiguous k-pairs) — no ldmatrix.
#define HS 40   // smem stride in halves; banks (20g+tig)%32 all-distinct

__global__ void __launch_bounds__(256) gemm_f16_kernel(
        const __half* __restrict__ A, const __half* __restrict__ Wt,
        const float* __restrict__ bias, __half* __restrict__ C,
        int N, int K, int act)
{
    __shared__ __half As[128 * HS];
    __shared__ __half Bs[128 * HS];

    int tid  = threadIdx.x;
    int w    = tid >> 5, lane = tid & 31;
    int g    = lane >> 2, tig = lane & 3;
    int wm   = w >> 1,  wn = w & 1;
    int rowb = blockIdx.y * 128;
    int colb = blockIdx.x * 128;

    int sr = tid >> 1, sc = (tid & 1) * 16;
    const __half* Ag = A  + (long)(rowb + sr) * K + sc;
    const __half* Wg = Wt + (long)(colb + sr) * K + sc;

    float acc[2][8][4];
    #pragma unroll
    for (int mt = 0; mt < 2; mt++)
        #pragma unroll
        for (int nt = 0; nt < 8; nt++)
            #pragma unroll
            for (int r = 0; r < 4; r++) acc[mt][nt][r] = 0.0f;

    for (int kt = 0; kt < K; kt += 32) {
        __syncthreads();
        uint4 av0 = *(const uint4*)(Ag + kt);
        uint4 av1 = *(const uint4*)(Ag + kt + 8);
        uint4 wv0 = *(const uint4*)(Wg + kt);
        uint4 wv1 = *(const uint4*)(Wg + kt + 8);
        *(uint4*)&As[sr * HS + sc]     = av0;
        *(uint4*)&As[sr * HS + sc + 8] = av1;
        *(uint4*)&Bs[sr * HS + sc]     = wv0;
        *(uint4*)&Bs[sr * HS + sc + 8] = wv1;
        __syncthreads();

        #pragma unroll
        for (int ks = 0; ks < 2; ks++) {
            int k0 = ks * 16;
            // A fragment: a0=(m=g,k=2tig..+1) a1=(m=g+8,..) a2=(m=g,k+8) a3=(m=g+8,k+8)
            uint32_t a[2][4];
            #pragma unroll
            for (int mt = 0; mt < 2; mt++) {
                int r0 = wm * 32 + mt * 16 + g;
                a[mt][0] = *(const uint32_t*)&As[ r0      * HS + k0 + 2 * tig];
                a[mt][1] = *(const uint32_t*)&As[(r0 + 8) * HS + k0 + 2 * tig];
                a[mt][2] = *(const uint32_t*)&As[ r0      * HS + k0 + 8 + 2 * tig];
                a[mt][3] = *(const uint32_t*)&As[(r0 + 8) * HS + k0 + 8 + 2 * tig];
            }
            // B fragment: b0=(n=g,k=2tig..+1), b1=(n=g,k=2tig+8..+9)
            uint32_t b[8][2];
            #pragma unroll
            for (int nt = 0; nt < 8; nt++) {
                int n = wn * 64 + nt * 8 + g;
                b[nt][0] = *(const uint32_t*)&Bs[n * HS + k0 + 2 * tig];
                b[nt][1] = *(const uint32_t*)&Bs[n * HS + k0 + 8 + 2 * tig];
            }
            #pragma unroll
            for (int mt = 0; mt < 2; mt++)
                #pragma unroll
                for (int nt = 0; nt < 8; nt++)
                    mma_f16(acc[mt][nt], a[mt], b[nt]);
        }
    }

    #pragma unroll
    for (int mt = 0; mt < 2; mt++) {
        int row0 = rowb + wm * 32 + mt * 16 + g;
        #pragma unroll
        for (int nt = 0; nt < 8; nt++) {
            int col = colb + wn * 64 + nt * 8 + 2 * tig;
            float b0 = bias[col], b1 = bias[col + 1];
            float o0 = acc[mt][nt][0] + b0;
            float o1 = acc[mt][nt][1] + b1;
            float o2 = acc[mt][nt][2] + b0;
            float o3 = acc[mt][nt][3] + b1;
            if (act) { o0 = gelu_exact(o0); o1 = gelu_exact(o1);
                       o2 = gelu_exact(o2); o3 = gelu_exact(o3); }
            *(__half2*)&C[(long)row0 * N + col]       = __floats2half2_rn(o0, o1);
            *(__half2*)&C[(long)(row0 + 8) * N + col] = __floats2half2_rn(o2, o3);
        }
    }
}

// ---------------- kernel 3: fused fp16 attention, explicit LDS frags ---------
// One block per (b,h); 256 threads (8 warps); warp = 16 q-rows x 256 keys,
// 2 passes. sQ/sK: [row][d] stride 72; sV stored TRANSPOSED sVt[d][key]
// stride 264 so V B-fragments are contiguous key-pairs.
#define AS 72
#define VTS 264
#define ATTN_SMEM ((2 * Ss * AS + DHh * VTS) * 2 + Ss * 4)

__global__ void __launch_bounds__(256, 1) attn_f16_kernel(
        const __half* __restrict__ qkv, const int* __restrict__ ids,
        __half* __restrict__ ctx)
{
    extern __shared__ char smraw[];
    __half* sQ  = (__half*)smraw;            // 256 x 72
    __half* sK  = sQ + Ss * AS;              // 256 x 72
    __half* sVt = sK + Ss * AS;              // 64 x 264  (sVt[d][key])
    float* sBias = (float*)(sVt + DHh * VTS);

    int bh = blockIdx.x;
    int b = bh >> 2, h = bh & 3;
    int base = b * Ss, hoff = h * DHh;
    int tid = threadIdx.x;

    for (int idx = tid; idx < Ss * 8; idx += 256) {
        int r = idx >> 3, u = idx & 7;
        const __half* gp = qkv + (long)(base + r) * 768 + hoff + u * 8;
        *(uint4*)&sQ[r * AS + u * 8] = *(const uint4*)(gp);
        *(uint4*)&sK[r * AS + u * 8] = *(const uint4*)(gp + 256);
    }
    // V transposed staging: sVt[d][key] = V[key][d]
    for (int idx = tid; idx < Ss * DHh; idx += 256) {
        int r = idx >> 6, d = idx & 63;
        sVt[d * VTS + r] = qkv[(long)(base + r) * 768 + 512 + hoff + d];
    }
    if (tid < Ss) sBias[tid] = (ids[base + tid] > 0) ? 0.0f : -10000.0f;
    __syncthreads();

    int w = tid >> 5, lane = tid & 31;
    int g = lane >> 2, tig = lane & 3;
    const float scale = 0.125f;

    for (int pass = 0; pass < 2; pass++) {
        int m0 = pass * 128 + w * 16;
        int r0 = m0 + g, r1 = m0 + 8 + g;

        // ---- A frags for Q (4 ksteps of 16 over d=64), explicit loads ----
        uint32_t aS[4][4];
        #pragma unroll
        for (int kc = 0; kc < 4; kc++) {
            int c = kc * 16 + 2 * tig;
            aS[kc][0] = *(const uint32_t*)&sQ[ r0 * AS + c];
            aS[kc][1] = *(const uint32_t*)&sQ[ r1 * AS + c];
            aS[kc][2] = *(const uint32_t*)&sQ[ r0 * AS + c + 8];
            aS[kc][3] = *(const uint32_t*)&sQ[ r1 * AS + c + 8];
        }

        // ---- S = Q K^T ----
        float acc[32][4];
        #pragma unroll
        for (int nt = 0; nt < 32; nt++)
            #pragma unroll
            for (int r = 0; r < 4; r++) acc[nt][r] = 0.0f;

        #pragma unroll
        for (int kc = 0; kc < 4; kc++) {
            int c = kc * 16 + 2 * tig;
            #pragma unroll
            for (int nt = 0; nt < 32; nt++) {
                int n = nt * 8 + g;
                uint32_t bb[2];
                bb[0] = *(const uint32_t*)&sK[n * AS + c];
                bb[1] = *(const uint32_t*)&sK[n * AS + c + 8];
                mma_f16(acc[nt], aS[kc], bb);
            }
        }

        // ---- softmax (rows r0, r1 full 256 keys in-warp) ----
        float mx0 = -1e30f, mx1 = -1e30f;
        #pragma unroll
        for (int nt = 0; nt < 32; nt++) {
            int c0 = nt * 8 + 2 * tig, c1 = c0 + 1;
            float bp0 = sBias[c0], bp1 = sBias[c1];
            acc[nt][0] = acc[nt][0] * scale + ((c0 <= r0) ? bp0 : -10000.0f);
            acc[nt][1] = acc[nt][1] * scale + ((c1 <= r0) ? bp1 : -10000.0f);
            acc[nt][2] = acc[nt][2] * scale + ((c0 <= r1) ? bp0 : -10000.0f);
            acc[nt][3] = acc[nt][3] * scale + ((c1 <= r1) ? bp1 : -10000.0f);
            mx0 = fmaxf(mx0, fmaxf(acc[nt][0], acc[nt][1]));
            mx1 = fmaxf(mx1, fmaxf(acc[nt][2], acc[nt][3]));
        }
        mx0 = fmaxf(mx0, __shfl_xor_sync(0xffffffffu, mx0, 1));
        mx0 = fmaxf(mx0, __shfl_xor_sync(0xffffffffu, mx0, 2));
        mx1 = fmaxf(mx1, __shfl_xor_sync(0xffffffffu, mx1, 1));
        mx1 = fmaxf(mx1, __shfl_xor_sync(0xffffffffu, mx1, 2));

        float s0 = 0.0f, s1 = 0.0f;
        #pragma unroll
        for (int nt = 0; nt < 32; nt++) {
            acc[nt][0] = __expf(acc[nt][0] - mx0);
            acc[nt][1] = __expf(acc[nt][1] - mx0);
            acc[nt][2] = __expf(acc[nt][2] - mx1);
            acc[nt][3] = __expf(acc[nt][3] - mx1);
            s0 += acc[nt][0] + acc[nt][1];
            s1 += acc[nt][2] + acc[nt][3];
        }
        s0 += __shfl_xor_sync(0xffffffffu, s0, 1);
        s0 += __shfl_xor_sync(0xffffffffu, s0, 2);
        s1 += __shfl_xor_sync(0xffffffffu, s1, 1);
        s1 += __shfl_xor_sync(0xffffffffu, s1, 2);
        float i0 = 1.0f / s0, i1 = 1.0f / s1;

        // ---- ctx = P @ V : C-frag of S == A-frag of P (canonical fp16 trick);
        //      V B-frags = contiguous key-pairs from sVt[d][key]. ----
        float acc2[8][4];
        #pragma unroll
        for (int nt = 0; nt < 8; nt++)
            #pragma unroll
            for (int r = 0; r < 4; r++) acc2[nt][r] = 0.0f;

        #pragma unroll
        for (int kc = 0; kc < 16; kc++) {
            uint32_t a[4];
            a[0] = packh2(acc[2*kc][0]   * i0, acc[2*kc][1]   * i0); // (r0, key 2tig..+1)
            a[1] = packh2(acc[2*kc][2]   * i1, acc[2*kc][3]   * i1); // (r1, key 2tig..+1)
            a[2] = packh2(acc[2*kc+1][0] * i0, acc[2*kc+1][1] * i0); // (r0, key 2tig+8..)
            a[3] = packh2(acc[2*kc+1][2] * i1, acc[2*kc+1][3] * i1); // (r1, key 2tig+8..)
            int c = kc * 16 + 2 * tig;
            #pragma unroll
            for (int nt = 0; nt < 8; nt++) {
                int d = nt * 8 + g;                 // n index = output dim
                uint32_t bb[2];
                bb[0] = *(const uint32_t*)&sVt[d * VTS + c];
                bb[1] = *(const uint32_t*)&sVt[d * VTS + c + 8];
                mma_f16(acc2[nt], a, bb);
            }
        }

        long o0 = (long)(base + r0) * Dd + hoff;
        long o1 = (long)(base + r1) * Dd + hoff;
        #pragma unroll
        for (int nt = 0; nt < 8; nt++) {
            int d = nt * 8 + 2 * tig;
            *(__half2*)&ctx[o0 + d] = __floats2half2_rn(acc2[nt][0], acc2[nt][1]);
            *(__half2*)&ctx[o1 + d] = __floats2half2_rn(acc2[nt][2], acc2[nt][3]);
        }
    }
}

// ---------------- kernel 4: h = LN(t + x) (half io) ----------------
__global__ void __launch_bounds__(256) add_ln_kernel(
        const __half* __restrict__ a, const __half* __restrict__ bres,
        __half* __restrict__ out)
{
    long i = (long)blockIdx.x * Dd + threadIdx.x;
    float v = __half2float(a[i]) + __half2float(bres[i]);
    float2 st = rowStats256(v);
    out[i] = __float2half_rn((v - st.x) * st.y);
}

// ---------------- kernel 5: x = LN(f2); total += x ----------------
__global__ void __launch_bounds__(256) ln_acc_kernel(
        const __half* __restrict__ f2, __half* __restrict__ x,
        float* __restrict__ out)
{
    long i = (long)blockIdx.x * Dd + threadIdx.x;
    float v = __half2float(f2[i]);
    float2 st = rowStats256(v);
    float y = (v - st.x) * st.y;
    x[i] = __float2half_rn(y);
    out[i] += y;
}

// ---------------- launch ----------------
extern "C" void kernel_launch(void* const* d_in, const int* in_sizes, int n_in,
                              void* d_out, int out_size)
{
    const int*   ids      = (const int*)  d_in[0];
    const float* item_emb = (const float*)d_in[1];
    const float* pos_emb  = (const float*)d_in[2];
    const float* Wq = (const float*)d_in[3];  const float* bq = (const float*)d_in[4];
    const float* Wk = (const float*)d_in[5];  const float* bk = (const float*)d_in[6];
    const float* Wv = (const float*)d_in[7];  const float* bv = (const float*)d_in[8];
    const float* Wo = (const float*)d_in[9];  const float* bo = (const float*)d_in[10];
    const float* W1 = (const float*)d_in[11]; const float* b1 = (const float*)d_in[12];
    const float* W2 = (const float*)d_in[13]; const float* b2 = (const float*)d_in[14];
    float* out = (float*)d_out;

    __half *x, *qkv, *ctx, *t, *h, *f1, *f2;
    __half *wqkvt, *wot, *w1t, *w2t;
    float  *bqkv;
    cudaGetSymbolAddress((void**)&x,     g_xh);
    cudaGetSymbolAddress((void**)&qkv,   g_qkv);
    cudaGetSymbolAddress((void**)&ctx,   g_ctx);
    cudaGetSymbolAddress((void**)&t,     g_t);
    cudaGetSymbolAddress((void**)&h,     g_hh);
    cudaGetSymbolAddress((void**)&f1,    g_f1);
    cudaGetSymbolAddress((void**)&f2,    g_f2);
    cudaGetSymbolAddress((void**)&wqkvt, g_wqkvt);
    cudaGetSymbolAddress((void**)&wot,   g_wot);
    cudaGetSymbolAddress((void**)&w1t,   g_w1t);
    cudaGetSymbolAddress((void**)&w2t,   g_w2t);
    cudaGetSymbolAddress((void**)&bqkv,  g_bqkv);

    cudaFuncSetAttribute(attn_f16_kernel,
                         cudaFuncAttributeMaxDynamicSharedMemorySize, ATTN_SMEM);

    // ---- weight conversion (transpose to [N][K] half) ----
    dim3 wb(32, 8);
    for (int l = 0; l < Ll; l++) {
        wconv_kernel<<<dim3(8, 8),  wb>>>(Wq + (long)l*Dd*Dd, wqkvt + (long)l*768*Dd,           Dd, Dd);
        wconv_kernel<<<dim3(8, 8),  wb>>>(Wk + (long)l*Dd*Dd, wqkvt + (long)l*768*Dd + 256*Dd,  Dd, Dd);
        wconv_kernel<<<dim3(8, 8),  wb>>>(Wv + (long)l*Dd*Dd, wqkvt + (long)l*768*Dd + 512*Dd,  Dd, Dd);
        wconv_kernel<<<dim3(8, 8),  wb>>>(Wo + (long)l*Dd*Dd, wot + (long)l*Dd*Dd,  Dd, Dd);
        wconv_kernel<<<dim3(32, 8), wb>>>(W1 + (long)l*Dd*FF, w1t + (long)l*FF*Dd,  Dd, FF);
        wconv_kernel<<<dim3(8, 32), wb>>>(W2 + (long)l*FF*Dd, w2t + (long)l*Dd*FF,  FF, Dd);
    }
    bias_pack_kernel<<<Ll * 3, 256>>>(bq, bk, bv, bqkv);

    embed_ln_kernel<<<NROWS, 256>>>(ids, item_emb, pos_emb, x, out);

    dim3 gQKV(6, 512), gD(2, 512), gF(8, 512);

    for (int l = 0; l < Ll; l++) {
        gemm_f16_kernel<<<gQKV, 256>>>(x, wqkvt + (long)l*768*Dd, bqkv + l*768,
                                       qkv, 768, Dd, 0);

        attn_f16_kernel<<<Bb * Hh, 256, ATTN_SMEM>>>(qkv, ids, ctx);

        gemm_f16_kernel<<<gD, 256>>>(ctx, wot + (long)l*Dd*Dd, bo + l*Dd,
                                     t, Dd, Dd, 0);
        add_ln_kernel<<<NROWS, 256>>>(t, x, h);

        gemm_f16_kernel<<<gF, 256>>>(h, w1t + (long)l*FF*Dd, b1 + l*FF,
                                     f1, FF, Dd, 1);
        gemm_f16_kernel<<<gD, 256>>>(f1, w2t + (long)l*Dd*FF, b2 + l*Dd,
                                     f2, Dd, FF, 0);

        ln_acc_kernel<<<NROWS, 256>>>(f2, x, out);
    }
}